// round 16
// baseline (speedup 1.0000x reference)
#include <cuda_runtime.h>
#include <cuda_fp16.h>
#include <math.h>
#include <stdint.h>

#define D_MODEL     256
#define EXPERT_DIM  512
#define NUM_EXPERTS 8
#define T_TOKENS    4096
#define TILE_T      32
#define EGRID       296
#define ETHREADS    256

// u32 (half2) strides
#define XS_U32      132       // ≡4 mod 32 -> ldmatrix conflict-free
#define HS_U32      68        // per-chunk H row: 64 k2 + 4 pad (≡4 mod 32)
#define W1R_U32     136       // 128 data + 8 pad
#define W2R_U32     264       // 256 data + 8 pad

#define W1HSTG_U    (64 * W1R_U32)          // 8704 u32 = 34816 B
#define W2HSTG_U    (32 * W2R_U32)          // 8448 u32 = 33792 B
#define CHUNKBLOB_U (2 * W1HSTG_U + 2 * W2HSTG_U)   // 34304
#define EXPERT_U    (4 * CHUNKBLOB_U)               // 137216
#define NSLOT       2
#define NSTAGE      16                      // 4 chunks * (2 W1 + 2 W2)
#define SLOT_U32    W1HSTG_U                // 8704

#define XS_OFF      0
#define HS_OFF      (XS_OFF + TILE_T * XS_U32)          // 4224
#define WST_OFF     (HS_OFF + TILE_T * HS_U32)          // 6400
#define CTRL_OFF    (WST_OFF + NSLOT * SLOT_U32)        // 23808
#define SMEM_U32    (CTRL_OFF + 128)                    // ctrl: 4 mbv + 96 tok/wt/slot
#define SMEM_BYTES  (SMEM_U32 * 4)                      // 95744 B -> 2 blocks/SM

// ---- device scratch ----
__device__ int      g_cnt[NUM_EXPERTS];
__device__ int      g_tok [NUM_EXPERTS][T_TOKENS];
__device__ float    g_wt  [NUM_EXPERTS][T_TOKENS];
__device__ int      g_slot[NUM_EXPERTS][T_TOKENS];
__device__ float    g_scratch[2][T_TOKENS][D_MODEL];
__device__ __align__(128) uint32_t g_Wblob[NUM_EXPERTS * EXPERT_U];
__device__ int      g_done;
__device__ int      g_done2;

// ---------------------------------------------------------------------------
__device__ __forceinline__ uint32_t pack_h2(float lo, float hi) {
    __half2 h;
    h.x = __float2half_rn(lo);
    h.y = __float2half_rn(hi);
    return *reinterpret_cast<uint32_t*>(&h);
}

__device__ __forceinline__ void mma_f16(float c[4], const uint32_t a[4],
                                        uint32_t b0, uint32_t b1) {
    asm volatile(
        "mma.sync.aligned.m16n8k16.row.col.f32.f16.f16.f32 "
        "{%0,%1,%2,%3}, {%4,%5,%6,%7}, {%8,%9}, {%0,%1,%2,%3};\n"
        : "+f"(c[0]), "+f"(c[1]), "+f"(c[2]), "+f"(c[3])
        : "r"(a[0]), "r"(a[1]), "r"(a[2]), "r"(a[3]), "r"(b0), "r"(b1));
}

__device__ __forceinline__ void ldsm_x4(uint32_t a[4], uint32_t addr) {
    asm volatile(
        "ldmatrix.sync.aligned.m8n8.x4.shared.b16 {%0,%1,%2,%3}, [%4];"
        : "=r"(a[0]), "=r"(a[1]), "=r"(a[2]), "=r"(a[3]) : "r"(addr));
}

#define MBAR_INIT(mb, n)  asm volatile("mbarrier.init.shared.b64 [%0], %1;" :: "r"(mb), "r"(n) : "memory")
#define MBAR_EXPECT_TX(mb, tx) asm volatile("mbarrier.arrive.expect_tx.shared.b64 _, [%0], %1;" :: "r"(mb), "r"(tx) : "memory")

__device__ __forceinline__ void cp_bulk(uint32_t dst, const void* src,
                                        uint32_t bytes, uint32_t mbar) {
    asm volatile(
        "cp.async.bulk.shared::cta.global.mbarrier::complete_tx::bytes "
        "[%0], [%1], %2, [%3];"
        :: "r"(dst), "l"(src), "r"(bytes), "r"(mbar) : "memory");
}

#define MBAR_WAIT(mb, ph) do { \
    uint32_t _mb = (mb), _ph = (ph), _done; \
    asm volatile("{\n\t.reg .pred p;\n\t" \
        "mbarrier.try_wait.parity.acquire.cta.shared::cta.b64 p, [%1], %2;\n\t" \
        "selp.b32 %0, 1, 0, p;\n\t}" : "=r"(_done) : "r"(_mb), "r"(_ph) : "memory"); \
    if (!_done) { \
        asm volatile("{\n\t.reg .pred P1;\n\t" \
            "WL_%=:\n\t" \
            "mbarrier.try_wait.parity.acquire.cta.shared::cta.b64 P1, [%0], %1, 0x989680;\n\t" \
            "@P1 bra.uni WD_%=;\n\t" \
            "bra.uni WL_%=;\n\t" \
            "WD_%=:\n\t}" :: "r"(_mb), "r"(_ph) : "memory"); \
    } \
} while (0)

// ---------------------------------------------------------------------------
// Fused init: [0,512) route; [512,2560) pack W1 -> blob; [2560,4608) pack W2.
__global__ void init_kernel(const float* __restrict__ x,
                            const float* __restrict__ Wg,
                            const float* __restrict__ bg,
                            const float* __restrict__ bias,
                            const float* __restrict__ W1,
                            const float* __restrict__ W2) {
    int bid = blockIdx.x, tid = threadIdx.x;

    if (bid < 512) {
        int warp = (bid * 256 + tid) >> 5;
        int lane = tid & 31;
        int t = warp;
        const float* xr = x + (size_t)t * D_MODEL;
        float acc[NUM_EXPERTS];
#pragma unroll
        for (int e = 0; e < NUM_EXPERTS; e++) acc[e] = 0.f;
#pragma unroll
        for (int j = 0; j < D_MODEL / 32; j++) {
            int k = lane + j * 32;
            float xv = xr[k];
            const float4* wrow = (const float4*)(Wg + (size_t)k * NUM_EXPERTS);
            float4 w0 = wrow[0], w1 = wrow[1];
            acc[0] += xv * w0.x; acc[1] += xv * w0.y;
            acc[2] += xv * w0.z; acc[3] += xv * w0.w;
            acc[4] += xv * w1.x; acc[5] += xv * w1.y;
            acc[6] += xv * w1.z; acc[7] += xv * w1.w;
        }
#pragma unroll
        for (int e = 0; e < NUM_EXPERTS; e++)
#pragma unroll
            for (int off = 16; off > 0; off >>= 1)
                acc[e] += __shfl_xor_sync(0xffffffffu, acc[e], off);
        if (lane == 0) {
            float best = -INFINITY, second = -INFINITY;
            int b0 = 0, b1i = 0;
#pragma unroll
            for (int e = 0; e < NUM_EXPERTS; e++) {
                float v = acc[e] + bg[e] + bias[e];
                if (v > best)        { second = best; b1i = b0; best = v; b0 = e; }
                else if (v > second) { second = v; b1i = e; }
            }
            float e1  = expf(second - best);
            float inv = 1.f / (1.f + e1);
            int p0 = atomicAdd(&g_cnt[b0], 1);
            g_tok[b0][p0] = t; g_wt[b0][p0] = inv;      g_slot[b0][p0] = 0;
            int p1 = atomicAdd(&g_cnt[b1i], 1);
            g_tok[b1i][p1] = t; g_wt[b1i][p1] = e1 * inv; g_slot[b1i][p1] = 1;
        }
    } else if (bid < 2560) {
        int j = (bid - 512) * 256 + tid;
        int h  = j & 511;
        int k2 = (j >> 9) & 127;
        int e  = j >> 16;
        const float* src = W1 + (size_t)e * 131072 + (size_t)(2 * k2) * 512 + h;
        int c = h >> 7, col = h & 127;
        int kh = k2 >> 6, k2l = k2 & 63;
        g_Wblob[(size_t)e * EXPERT_U + c * CHUNKBLOB_U + kh * W1HSTG_U
                + k2l * W1R_U32 + col] = pack_h2(src[0], src[512]);
    } else {
        int j = (bid - 2560) * 256 + tid;
        int d  = j & 255;
        int k2 = (j >> 8) & 255;
        int e  = j >> 16;
        const float* src = W2 + (size_t)e * 131072 + (size_t)(2 * k2) * 256 + d;
        int c = k2 >> 6, k2c = k2 & 63;
        int kh = k2c >> 5, k2l = k2c & 31;
        g_Wblob[(size_t)e * EXPERT_U + c * CHUNKBLOB_U + 2 * W1HSTG_U
                + kh * W2HSTG_U + k2l * W2R_U32 + d] = pack_h2(src[0], src[256]);
    }
}

// ---------------------------------------------------------------------------
// 296 blocks x 256 threads, 2 blocks/SM (independent pipelines). 8 warps =
// 2m x 4n over 32 tokens. 16 stages/item, 2-slot TMA ring, look-ahead 1.
__global__ void __launch_bounds__(ETHREADS, 2)
expert_kernel(const float* __restrict__ x,
              const float* __restrict__ b1,
              const float* __restrict__ b2,
              float* __restrict__ out) {
    extern __shared__ uint32_t sm[];
    uint32_t* Xs  = sm + XS_OFF;        // [32][132]
    uint32_t* Hs  = sm + HS_OFF;        // [32][68]
    uint32_t* Wst = sm + WST_OFF;       // [2][8704]
    uint64_t* mbv = (uint64_t*)(sm + CTRL_OFF);
    int*   s_tok  = (int*)(sm + CTRL_OFF + 8);
    float* s_wt   = (float*)(s_tok + TILE_T);
    int*   s_slot = (int*)(s_wt + TILE_T);

    int tid  = threadIdx.x;
    int wid  = tid >> 5;
    int wm   = wid >> 2;        // 0..1: rows 16*wm..+16
    int wn   = wid & 3;         // 0..3
    int lane = tid & 31;
    int g = lane >> 2, t = lane & 3;

    uint32_t wst_sa  = (uint32_t)__cvta_generic_to_shared(Wst);
    uint32_t xs_sa   = (uint32_t)__cvta_generic_to_shared(Xs);
    uint32_t hs_sa   = (uint32_t)__cvta_generic_to_shared(Hs);
    uint32_t mbar_sa = (uint32_t)__cvta_generic_to_shared(mbv);

    int lrow = lane & 15;
    int lcol = (lane >> 4) * 16;
    uint32_t xa0 = xs_sa + (uint32_t)((wm * 16 + lrow) * (XS_U32 * 4)) + lcol;
    uint32_t ha0 = hs_sa + (uint32_t)((wm * 16 + lrow) * (HS_U32 * 4)) + lcol;

    if (tid == 0) {
#pragma unroll
        for (int i = 0; i < NSLOT; i++) MBAR_INIT(mbar_sa + i * 8, 1);
    }
    __syncthreads();

    // inline scheduler
    int cnt[NUM_EXPERTS], off[NUM_EXPERTS + 1];
    off[0] = 0;
#pragma unroll
    for (int e = 0; e < NUM_EXPERTS; e++) {
        cnt[e] = g_cnt[e];
        off[e + 1] = off[e] + (cnt[e] + TILE_T - 1) / TILE_T;
    }
    int total = off[NUM_EXPERTS];

    int gs = 0;   // absolute stage counter: slot = a&1, phase = (a>>1)&1

    for (int it = blockIdx.x; it < total; it += EGRID) {
        int e = 0;
#pragma unroll
        for (int k = 1; k < NUM_EXPERTS; k++)
            if (it >= off[k]) e = k;
        int start = (it - off[e]) * TILE_T;
        int m = min(TILE_T, cnt[e] - start);

        const uint32_t* blob = g_Wblob + (size_t)e * EXPERT_U;
        const float* b1e = b1 + e * EXPERT_DIM;
        const float* b2e = b2 + e * D_MODEL;

        // stage s (0..15): c = s>>2, j = s&3.
        auto issue_stage = [&](int s) {      // tid 0 only
            int a = gs + s;
            int slot = a & 1;
            int c = s >> 2, j = s & 3;
            uint32_t dst = wst_sa + (uint32_t)(slot * SLOT_U32) * 4u;
            const uint32_t* src;
            uint32_t bytes;
            if (j < 2) {
                src = blob + c * CHUNKBLOB_U + j * W1HSTG_U;
                bytes = W1HSTG_U * 4u;
            } else {
                src = blob + c * CHUNKBLOB_U + 2 * W1HSTG_U + (j - 2) * W2HSTG_U;
                bytes = W2HSTG_U * 4u;
            }
            uint32_t mb = mbar_sa + slot * 8;
            MBAR_EXPECT_TX(mb, bytes);
            cp_bulk(dst, src, bytes, mb);
        };

        __syncthreads();     // prev item's compute fully done -> slot reuse safe
        if (tid < TILE_T) {
            if (tid < m) {
                s_tok[tid]  = g_tok [e][start + tid];
                s_wt[tid]   = g_wt  [e][start + tid];
                s_slot[tid] = g_slot[e][start + tid];
            } else {
                s_tok[tid] = 0; s_wt[tid] = 0.f; s_slot[tid] = 0;
            }
        }
        if (tid == 0) issue_stage(0);
        __syncthreads();

        // gather X tile -> half2 pairs: 32 rows x 64 float4 = 2048
#pragma unroll
        for (int i = 0; i < 8; i++) {
            int idx = tid + i * ETHREADS;
            int row = idx >> 6, q = idx & 63;
            float4 v = make_float4(0.f, 0.f, 0.f, 0.f);
            if (row < m)
                v = ((const float4*)(x + (size_t)s_tok[row] * D_MODEL))[q];
            uint2 p;
            p.x = pack_h2(v.x, v.y);
            p.y = pack_h2(v.z, v.w);
            *((uint2*)&Xs[row * XS_U32 + q * 2]) = p;
        }

        float acc2[8][4];
#pragma unroll
        for (int f = 0; f < 8; f++)
#pragma unroll
            for (int r = 0; r < 4; r++) acc2[f][r] = 0.f;
        float c1[4][4];      // GEMM1 n-slice 32 cols

        for (int s = 0; s < NSTAGE; s++) {
            int a = gs + s;
            int slot = a & 1;
            MBAR_WAIT(mbar_sa + slot * 8, (a >> 1) & 1);
            __syncthreads();             // all warps done stage s-1 -> other slot free
            if (tid == 0 && s + 1 < NSTAGE) issue_stage(s + 1);

            int c = s >> 2, j = s & 3;
            const uint32_t* Ws = Wst + slot * SLOT_U32;

            if (j < 2) {
                // ====== GEMM1 K-half j: 8 ksteps, n-slice 32 cols ======
                if (j == 0) {
#pragma unroll
                    for (int f = 0; f < 4; f++)
#pragma unroll
                        for (int r = 0; r < 4; r++) c1[f][r] = 0.f;
                }
#pragma unroll
                for (int ks = 0; ks < 8; ks++) {
                    uint32_t a0[4];
                    ldsm_x4(a0, xa0 + (j * 8 + ks) * 32);
#pragma unroll
                    for (int f = 0; f < 4; f++) {
                        int col = wn * 32 + 8 * f + g;
                        uint32_t b0 = Ws[(ks * 8 + t) * W1R_U32 + col];
                        uint32_t bv = Ws[(ks * 8 + t + 4) * W1R_U32 + col];
                        mma_f16(c1[f], a0, b0, bv);
                    }
                }
                if (j == 1) {
                    // bias + relu -> Hs (per-chunk, 128 cols wide)
#pragma unroll
                    for (int f = 0; f < 4; f++) {
                        float bv0 = b1e[c * 128 + wn * 32 + 8 * f + 2 * t];
                        float bv1 = b1e[c * 128 + wn * 32 + 8 * f + 2 * t + 1];
                        int k2b = wn * 16 + 4 * f + t;
                        int r0 = wm * 16 + g;
                        Hs[r0 * HS_U32 + k2b] =
                            pack_h2(fmaxf(c1[f][0] + bv0, 0.f),
                                    fmaxf(c1[f][1] + bv1, 0.f));
                        Hs[(r0 + 8) * HS_U32 + k2b] =
                            pack_h2(fmaxf(c1[f][2] + bv0, 0.f),
                                    fmaxf(c1[f][3] + bv1, 0.f));
                    }
                }
            } else {
                // ====== GEMM2 K-half j-2: 4 ksteps, n-slice 64 cols ======
                int kh = j - 2;
#pragma unroll
                for (int ks = 0; ks < 4; ks++) {
                    uint32_t a0[4];
                    ldsm_x4(a0, ha0 + (kh * 4 + ks) * 32);
#pragma unroll
                    for (int f = 0; f < 8; f++) {
                        int col = wn * 64 + 8 * f + g;
                        uint32_t b0 = Ws[(ks * 8 + t) * W2R_U32 + col];
                        uint32_t bv = Ws[(ks * 8 + t + 4) * W2R_U32 + col];
                        mma_f16(acc2[f], a0, b0, bv);
                    }
                }
            }
        }
        gs += NSTAGE;

        // ---- epilogue: scratch[slot][tok][col] = w * (acc + b2) ----
#pragma unroll
        for (int hr = 0; hr < 2; hr++) {
            int r = wm * 16 + g + 8 * hr;
            if (r < m) {
                float wgt = s_wt[r];
                float* op = &g_scratch[s_slot[r]][s_tok[r]][0];
#pragma unroll
                for (int f = 0; f < 8; f++) {
                    int col = wn * 64 + 8 * f + 2 * t;
                    float2 o;
                    o.x = wgt * (acc2[f][2 * hr + 0] + b2e[col]);
                    o.y = wgt * (acc2[f][2 * hr + 1] + b2e[col + 1]);
                    *((float2*)(op + col)) = o;
                }
            }
        }
    }

    // ================= spin barrier + fused combine =================
    __threadfence();
    __syncthreads();
    if (tid == 0) {
        atomicAdd(&g_done, 1);
        while (*((volatile int*)&g_done) < EGRID) { }
    }
    __syncthreads();
    __threadfence();

    const float4* s0 = (const float4*)g_scratch[0];
    const float4* s1 = (const float4*)g_scratch[1];
    float4* o4 = (float4*)out;
    const int N4 = T_TOKENS * D_MODEL / 4;
    for (int i = blockIdx.x * ETHREADS + tid; i < N4; i += EGRID * ETHREADS) {
        float4 a = s0[i], b = s1[i];
        float4 o;
        o.x = a.x + b.x; o.y = a.y + b.y; o.z = a.z + b.z; o.w = a.w + b.w;
        o4[i] = o;
    }

    // ---- last block resets counters for next graph replay ----
    __threadfence();
    __syncthreads();
    if (tid == 0) {
        int v = atomicAdd(&g_done2, 1);
        if (v == EGRID - 1) {
            g_done = 0; g_done2 = 0;
#pragma unroll
            for (int e = 0; e < NUM_EXPERTS; e++) g_cnt[e] = 0;
        }
    }
}

// ---------------------------------------------------------------------------
extern "C" void kernel_launch(void* const* d_in, const int* in_sizes, int n_in,
                              void* d_out, int out_size) {
    const float* x    = (const float*)d_in[0];
    const float* Wg   = (const float*)d_in[1];
    const float* bg   = (const float*)d_in[2];
    const float* bias = (const float*)d_in[3];
    const float* W1   = (const float*)d_in[4];
    const float* b1   = (const float*)d_in[5];
    const float* W2   = (const float*)d_in[6];
    const float* b2   = (const float*)d_in[7];
    float* out = (float*)d_out;

    cudaFuncSetAttribute(expert_kernel,
                         cudaFuncAttributeMaxDynamicSharedMemorySize, SMEM_BYTES);

    init_kernel<<<4608, 256>>>(x, Wg, bg, bias, W1, W2);
    expert_kernel<<<EGRID, ETHREADS, SMEM_BYTES>>>(x, b1, b2, out);
}

// round 17
// speedup vs baseline: 1.0073x; 1.0073x over previous
#include <cuda_runtime.h>
#include <cuda_fp16.h>
#include <math.h>
#include <stdint.h>

#define D_MODEL     256
#define EXPERT_DIM  512
#define NUM_EXPERTS 8
#define T_TOKENS    4096
#define TILE_T      32
#define EGRID       296
#define ETHREADS    256

// u32 (half2) strides
#define XS_U32      132       // ≡4 mod 32 -> ldmatrix conflict-free
#define HS_U32      68        // per-chunk H row: 64 k2 + 4 pad (≡4 mod 32)
#define W1R_U32     136       // 128 data + 8 pad
#define W2R_U32     264       // 256 data + 8 pad

#define W1HSTG_U    (64 * W1R_U32)          // 8704 u32 = 34816 B
#define W2HSTG_U    (32 * W2R_U32)          // 8448 u32 = 33792 B
#define CHUNKBLOB_U (2 * W1HSTG_U + 2 * W2HSTG_U)   // 34304
#define EXPERT_U    (4 * CHUNKBLOB_U)               // 137216
#define NSLOT       2
#define NSTAGE      16                      // 4 chunks * (2 W1 + 2 W2)
#define SLOT_U32    W1HSTG_U                // 8704

#define XS_OFF      0
#define HS_OFF      (XS_OFF + TILE_T * XS_U32)          // 4224
#define WST_OFF     (HS_OFF + TILE_T * HS_U32)          // 6400
#define CTRL_OFF    (WST_OFF + NSLOT * SLOT_U32)        // 23808
#define SMEM_U32    (CTRL_OFF + 160)
#define SMEM_BYTES  (SMEM_U32 * 4)                      // 95872 B -> 2 blocks/SM

// ---- device scratch ----
__device__ int      g_cnt[NUM_EXPERTS];
__device__ int      g_tok [NUM_EXPERTS][T_TOKENS];
__device__ float    g_wt  [NUM_EXPERTS][T_TOKENS];
__device__ int      g_slot[NUM_EXPERTS][T_TOKENS];
__device__ float    g_scratch[2][T_TOKENS][D_MODEL];
__device__ __align__(128) uint32_t g_Wblob[NUM_EXPERTS * EXPERT_U];
__device__ int      g_done;
__device__ int      g_done2;

// ---------------------------------------------------------------------------
__device__ __forceinline__ uint32_t pack_h2(float lo, float hi) {
    __half2 h;
    h.x = __float2half_rn(lo);
    h.y = __float2half_rn(hi);
    return *reinterpret_cast<uint32_t*>(&h);
}

__device__ __forceinline__ void mma_f16(float c[4], const uint32_t a[4],
                                        uint32_t b0, uint32_t b1) {
    asm volatile(
        "mma.sync.aligned.m16n8k16.row.col.f32.f16.f16.f32 "
        "{%0,%1,%2,%3}, {%4,%5,%6,%7}, {%8,%9}, {%0,%1,%2,%3};\n"
        : "+f"(c[0]), "+f"(c[1]), "+f"(c[2]), "+f"(c[3])
        : "r"(a[0]), "r"(a[1]), "r"(a[2]), "r"(a[3]), "r"(b0), "r"(b1));
}

__device__ __forceinline__ void ldsm_x4(uint32_t a[4], uint32_t addr) {
    asm volatile(
        "ldmatrix.sync.aligned.m8n8.x4.shared.b16 {%0,%1,%2,%3}, [%4];"
        : "=r"(a[0]), "=r"(a[1]), "=r"(a[2]), "=r"(a[3]) : "r"(addr));
}

#define MBAR_INIT(mb, n)  asm volatile("mbarrier.init.shared.b64 [%0], %1;" :: "r"(mb), "r"(n) : "memory")
#define MBAR_EXPECT_TX(mb, tx) asm volatile("mbarrier.arrive.expect_tx.shared.b64 _, [%0], %1;" :: "r"(mb), "r"(tx) : "memory")

__device__ __forceinline__ void cp_bulk(uint32_t dst, const void* src,
                                        uint32_t bytes, uint32_t mbar) {
    asm volatile(
        "cp.async.bulk.shared::cta.global.mbarrier::complete_tx::bytes "
        "[%0], [%1], %2, [%3];"
        :: "r"(dst), "l"(src), "r"(bytes), "r"(mbar) : "memory");
}

#define MBAR_WAIT(mb, ph) do { \
    uint32_t _mb = (mb), _ph = (ph), _done; \
    asm volatile("{\n\t.reg .pred p;\n\t" \
        "mbarrier.try_wait.parity.acquire.cta.shared::cta.b64 p, [%1], %2;\n\t" \
        "selp.b32 %0, 1, 0, p;\n\t}" : "=r"(_done) : "r"(_mb), "r"(_ph) : "memory"); \
    if (!_done) { \
        asm volatile("{\n\t.reg .pred P1;\n\t" \
            "WL_%=:\n\t" \
            "mbarrier.try_wait.parity.acquire.cta.shared::cta.b64 P1, [%0], %1, 0x989680;\n\t" \
            "@P1 bra.uni WD_%=;\n\t" \
            "bra.uni WL_%=;\n\t" \
            "WD_%=:\n\t}" :: "r"(_mb), "r"(_ph) : "memory"); \
    } \
} while (0)

// ---------------------------------------------------------------------------
// Fused init: [0,512) route; [512,2560) pack W1 -> blob; [2560,4608) pack W2.
__global__ void init_kernel(const float* __restrict__ x,
                            const float* __restrict__ Wg,
                            const float* __restrict__ bg,
                            const float* __restrict__ bias,
                            const float* __restrict__ W1,
                            const float* __restrict__ W2) {
    int bid = blockIdx.x, tid = threadIdx.x;

    if (bid < 512) {
        int warp = (bid * 256 + tid) >> 5;
        int lane = tid & 31;
        int t = warp;
        const float* xr = x + (size_t)t * D_MODEL;
        float acc[NUM_EXPERTS];
#pragma unroll
        for (int e = 0; e < NUM_EXPERTS; e++) acc[e] = 0.f;
#pragma unroll
        for (int j = 0; j < D_MODEL / 32; j++) {
            int k = lane + j * 32;
            float xv = xr[k];
            const float4* wrow = (const float4*)(Wg + (size_t)k * NUM_EXPERTS);
            float4 w0 = wrow[0], w1 = wrow[1];
            acc[0] += xv * w0.x; acc[1] += xv * w0.y;
            acc[2] += xv * w0.z; acc[3] += xv * w0.w;
            acc[4] += xv * w1.x; acc[5] += xv * w1.y;
            acc[6] += xv * w1.z; acc[7] += xv * w1.w;
        }
#pragma unroll
        for (int e = 0; e < NUM_EXPERTS; e++)
#pragma unroll
            for (int off = 16; off > 0; off >>= 1)
                acc[e] += __shfl_xor_sync(0xffffffffu, acc[e], off);
        if (lane == 0) {
            float best = -INFINITY, second = -INFINITY;
            int b0 = 0, b1i = 0;
#pragma unroll
            for (int e = 0; e < NUM_EXPERTS; e++) {
                float v = acc[e] + bg[e] + bias[e];
                if (v > best)        { second = best; b1i = b0; best = v; b0 = e; }
                else if (v > second) { second = v; b1i = e; }
            }
            float e1  = expf(second - best);
            float inv = 1.f / (1.f + e1);
            int p0 = atomicAdd(&g_cnt[b0], 1);
            g_tok[b0][p0] = t; g_wt[b0][p0] = inv;      g_slot[b0][p0] = 0;
            int p1 = atomicAdd(&g_cnt[b1i], 1);
            g_tok[b1i][p1] = t; g_wt[b1i][p1] = e1 * inv; g_slot[b1i][p1] = 1;
        }
    } else if (bid < 2560) {
        int j = (bid - 512) * 256 + tid;
        int h  = j & 511;
        int k2 = (j >> 9) & 127;
        int e  = j >> 16;
        const float* src = W1 + (size_t)e * 131072 + (size_t)(2 * k2) * 512 + h;
        int c = h >> 7, col = h & 127;
        int kh = k2 >> 6, k2l = k2 & 63;
        g_Wblob[(size_t)e * EXPERT_U + c * CHUNKBLOB_U + kh * W1HSTG_U
                + k2l * W1R_U32 + col] = pack_h2(src[0], src[512]);
    } else {
        int j = (bid - 2560) * 256 + tid;
        int d  = j & 255;
        int k2 = (j >> 8) & 255;
        int e  = j >> 16;
        const float* src = W2 + (size_t)e * 131072 + (size_t)(2 * k2) * 256 + d;
        int c = k2 >> 6, k2c = k2 & 63;
        int kh = k2c >> 5, k2l = k2c & 31;
        g_Wblob[(size_t)e * EXPERT_U + c * CHUNKBLOB_U + 2 * W1HSTG_U
                + kh * W2HSTG_U + k2l * W2R_U32 + d] = pack_h2(src[0], src[256]);
    }
}

// ---------------------------------------------------------------------------
// 296 blocks x 256 threads, 2 blocks/SM. 8 warps = 2m x 4n over 32 tokens.
// 16 stages/item, 2-slot TMA ring, software-pipelined inner loops,
// scheduler in shared memory.
__global__ void __launch_bounds__(ETHREADS, 2)
expert_kernel(const float* __restrict__ x,
              const float* __restrict__ b1,
              const float* __restrict__ b2,
              float* __restrict__ out) {
    extern __shared__ uint32_t sm[];
    uint32_t* Xs  = sm + XS_OFF;        // [32][132]
    uint32_t* Hs  = sm + HS_OFF;        // [32][68]
    uint32_t* Wst = sm + WST_OFF;       // [2][8704]
    uint64_t* mbv = (uint64_t*)(sm + CTRL_OFF);
    int*   s_tok  = (int*)(sm + CTRL_OFF + 8);
    float* s_wt   = (float*)(s_tok + TILE_T);
    int*   s_slot = (int*)(s_wt + TILE_T);
    int*   s_cnt  = (int*)(s_slot + TILE_T);   // 8
    int*   s_off  = (int*)(s_cnt + 8);         // 9

    int tid  = threadIdx.x;
    int wid  = tid >> 5;
    int wm   = wid >> 2;        // 0..1: rows 16*wm..+16
    int wn   = wid & 3;         // 0..3
    int lane = tid & 31;
    int g = lane >> 2, t = lane & 3;

    uint32_t wst_sa  = (uint32_t)__cvta_generic_to_shared(Wst);
    uint32_t xs_sa   = (uint32_t)__cvta_generic_to_shared(Xs);
    uint32_t hs_sa   = (uint32_t)__cvta_generic_to_shared(Hs);
    uint32_t mbar_sa = (uint32_t)__cvta_generic_to_shared(mbv);

    int lrow = lane & 15;
    int lcol = (lane >> 4) * 16;
    uint32_t xa0 = xs_sa + (uint32_t)((wm * 16 + lrow) * (XS_U32 * 4)) + lcol;
    uint32_t ha0 = hs_sa + (uint32_t)((wm * 16 + lrow) * (HS_U32 * 4)) + lcol;

    if (tid == 0) {
#pragma unroll
        for (int i = 0; i < NSLOT; i++) MBAR_INIT(mbar_sa + i * 8, 1);
    }
    if (tid < NUM_EXPERTS) s_cnt[tid] = g_cnt[tid];
    __syncthreads();
    if (tid == 0) {
        int tt = 0;
#pragma unroll
        for (int e = 0; e < NUM_EXPERTS; e++) {
            s_off[e] = tt;
            tt += (s_cnt[e] + TILE_T - 1) / TILE_T;
        }
        s_off[NUM_EXPERTS] = tt;
    }
    __syncthreads();
    int total = s_off[NUM_EXPERTS];

    int gs = 0;   // absolute stage counter: slot = a&1, phase = (a>>1)&1

    for (int it = blockIdx.x; it < total; it += EGRID) {
        int e = 0;
#pragma unroll
        for (int k = 1; k < NUM_EXPERTS; k++)
            if (it >= s_off[k]) e = k;
        int start = (it - s_off[e]) * TILE_T;
        int m = min(TILE_T, s_cnt[e] - start);

        const uint32_t* blob = g_Wblob + (size_t)e * EXPERT_U;
        const float* b1e = b1 + e * EXPERT_DIM;
        const float* b2e = b2 + e * D_MODEL;

        // stage s (0..15): c = s>>2, j = s&3.
        auto issue_stage = [&](int s) {      // tid 0 only
            int a = gs + s;
            int slot = a & 1;
            int c = s >> 2, j = s & 3;
            uint32_t dst = wst_sa + (uint32_t)(slot * SLOT_U32) * 4u;
            const uint32_t* src;
            uint32_t bytes;
            if (j < 2) {
                src = blob + c * CHUNKBLOB_U + j * W1HSTG_U;
                bytes = W1HSTG_U * 4u;
            } else {
                src = blob + c * CHUNKBLOB_U + 2 * W1HSTG_U + (j - 2) * W2HSTG_U;
                bytes = W2HSTG_U * 4u;
            }
            uint32_t mb = mbar_sa + slot * 8;
            MBAR_EXPECT_TX(mb, bytes);
            cp_bulk(dst, src, bytes, mb);
        };

        __syncthreads();     // prev item's compute fully done -> slot reuse safe
        if (tid < TILE_T) {
            if (tid < m) {
                s_tok[tid]  = g_tok [e][start + tid];
                s_wt[tid]   = g_wt  [e][start + tid];
                s_slot[tid] = g_slot[e][start + tid];
            } else {
                s_tok[tid] = 0; s_wt[tid] = 0.f; s_slot[tid] = 0;
            }
        }
        if (tid == 0) issue_stage(0);
        __syncthreads();

        // gather X tile -> half2 pairs: 32 rows x 64 float4 = 2048
#pragma unroll
        for (int i = 0; i < 8; i++) {
            int idx = tid + i * ETHREADS;
            int row = idx >> 6, q = idx & 63;
            float4 v = make_float4(0.f, 0.f, 0.f, 0.f);
            if (row < m)
                v = ((const float4*)(x + (size_t)s_tok[row] * D_MODEL))[q];
            uint2 p;
            p.x = pack_h2(v.x, v.y);
            p.y = pack_h2(v.z, v.w);
            *((uint2*)&Xs[row * XS_U32 + q * 2]) = p;
        }

        float acc2[8][4];
#pragma unroll
        for (int f = 0; f < 8; f++)
#pragma unroll
            for (int r = 0; r < 4; r++) acc2[f][r] = 0.f;
        float c1[4][4];      // GEMM1 n-slice 32 cols

        for (int s = 0; s < NSTAGE; s++) {
            int a = gs + s;
            int slot = a & 1;
            MBAR_WAIT(mbar_sa + slot * 8, (a >> 1) & 1);
            __syncthreads();             // all warps done stage s-1 -> other slot free
            if (tid == 0 && s + 1 < NSTAGE) issue_stage(s + 1);

            int c = s >> 2, j = s & 3;
            const uint32_t* Ws = Wst + slot * SLOT_U32;

            if (j < 2) {
                // ====== GEMM1 K-half j: 8 ksteps, sw-pipelined ======
                if (j == 0) {
#pragma unroll
                    for (int f = 0; f < 4; f++)
#pragma unroll
                        for (int r = 0; r < 4; r++) c1[f][r] = 0.f;
                }
                uint32_t aA[4], bA[8];
                ldsm_x4(aA, xa0 + (j * 8) * 32);
#pragma unroll
                for (int f = 0; f < 4; f++) {
                    int cc = wn * 32 + 8 * f + g;
                    bA[2 * f]     = Ws[t * W1R_U32 + cc];
                    bA[2 * f + 1] = Ws[(t + 4) * W1R_U32 + cc];
                }
#pragma unroll
                for (int ks = 0; ks < 8; ks++) {
                    uint32_t aB[4], bB[8];
                    if (ks < 7) {
                        ldsm_x4(aB, xa0 + (j * 8 + ks + 1) * 32);
#pragma unroll
                        for (int f = 0; f < 4; f++) {
                            int cc = wn * 32 + 8 * f + g;
                            bB[2 * f]     = Ws[((ks + 1) * 8 + t) * W1R_U32 + cc];
                            bB[2 * f + 1] = Ws[((ks + 1) * 8 + t + 4) * W1R_U32 + cc];
                        }
                    }
#pragma unroll
                    for (int f = 0; f < 4; f++)
                        mma_f16(c1[f], aA, bA[2 * f], bA[2 * f + 1]);
#pragma unroll
                    for (int q = 0; q < 4; q++) aA[q] = aB[q];
#pragma unroll
                    for (int q = 0; q < 8; q++) bA[q] = bB[q];
                }
                if (j == 1) {
                    // bias + relu -> Hs (per-chunk, 128 cols wide)
#pragma unroll
                    for (int f = 0; f < 4; f++) {
                        float bv0 = b1e[c * 128 + wn * 32 + 8 * f + 2 * t];
                        float bv1 = b1e[c * 128 + wn * 32 + 8 * f + 2 * t + 1];
                        int k2b = wn * 16 + 4 * f + t;
                        int r0 = wm * 16 + g;
                        Hs[r0 * HS_U32 + k2b] =
                            pack_h2(fmaxf(c1[f][0] + bv0, 0.f),
                                    fmaxf(c1[f][1] + bv1, 0.f));
                        Hs[(r0 + 8) * HS_U32 + k2b] =
                            pack_h2(fmaxf(c1[f][2] + bv0, 0.f),
                                    fmaxf(c1[f][3] + bv1, 0.f));
                    }
                }
            } else {
                // ====== GEMM2 K-half j-2: 4 ksteps, sw-pipelined ======
                int kh = j - 2;
                uint32_t aA[4], bA[16];
                ldsm_x4(aA, ha0 + (kh * 4) * 32);
#pragma unroll
                for (int f = 0; f < 8; f++) {
                    int cc = wn * 64 + 8 * f + g;
                    bA[2 * f]     = Ws[t * W2R_U32 + cc];
                    bA[2 * f + 1] = Ws[(t + 4) * W2R_U32 + cc];
                }
#pragma unroll
                for (int ks = 0; ks < 4; ks++) {
                    uint32_t aB[4], bB[16];
                    if (ks < 3) {
                        ldsm_x4(aB, ha0 + (kh * 4 + ks + 1) * 32);
#pragma unroll
                        for (int f = 0; f < 8; f++) {
                            int cc = wn * 64 + 8 * f + g;
                            bB[2 * f]     = Ws[((ks + 1) * 8 + t) * W2R_U32 + cc];
                            bB[2 * f + 1] = Ws[((ks + 1) * 8 + t + 4) * W2R_U32 + cc];
                        }
                    }
#pragma unroll
                    for (int f = 0; f < 8; f++)
                        mma_f16(acc2[f], aA, bA[2 * f], bA[2 * f + 1]);
#pragma unroll
                    for (int q = 0; q < 4; q++) aA[q] = aB[q];
#pragma unroll
                    for (int q = 0; q < 16; q++) bA[q] = bB[q];
                }
            }
        }
        gs += NSTAGE;

        // ---- epilogue: scratch[slot][tok][col] = w * (acc + b2) ----
#pragma unroll
        for (int hr = 0; hr < 2; hr++) {
            int r = wm * 16 + g + 8 * hr;
            if (r < m) {
                float wgt = s_wt[r];
                float* op = &g_scratch[s_slot[r]][s_tok[r]][0];
#pragma unroll
                for (int f = 0; f < 8; f++) {
                    int col = wn * 64 + 8 * f + 2 * t;
                    float2 o;
                    o.x = wgt * (acc2[f][2 * hr + 0] + b2e[col]);
                    o.y = wgt * (acc2[f][2 * hr + 1] + b2e[col + 1]);
                    *((float2*)(op + col)) = o;
                }
            }
        }
    }

    // ================= spin barrier + fused combine =================
    __threadfence();
    __syncthreads();
    if (tid == 0) {
        atomicAdd(&g_done, 1);
        while (*((volatile int*)&g_done) < EGRID) { }
    }
    __syncthreads();
    __threadfence();

    const float4* s0 = (const float4*)g_scratch[0];
    const float4* s1 = (const float4*)g_scratch[1];
    float4* o4 = (float4*)out;
    const int N4 = T_TOKENS * D_MODEL / 4;
    for (int i = blockIdx.x * ETHREADS + tid; i < N4; i += EGRID * ETHREADS) {
        float4 a = s0[i], b = s1[i];
        float4 o;
        o.x = a.x + b.x; o.y = a.y + b.y; o.z = a.z + b.z; o.w = a.w + b.w;
        o4[i] = o;
    }

    // ---- last block resets counters for next graph replay ----
    __threadfence();
    __syncthreads();
    if (tid == 0) {
        int v = atomicAdd(&g_done2, 1);
        if (v == EGRID - 1) {
            g_done = 0; g_done2 = 0;
#pragma unroll
            for (int e = 0; e < NUM_EXPERTS; e++) g_cnt[e] = 0;
        }
    }
}

// ---------------------------------------------------------------------------
extern "C" void kernel_launch(void* const* d_in, const int* in_sizes, int n_in,
                              void* d_out, int out_size) {
    const float* x    = (const float*)d_in[0];
    const float* Wg   = (const float*)d_in[1];
    const float* bg   = (const float*)d_in[2];
    const float* bias = (const float*)d_in[3];
    const float* W1   = (const float*)d_in[4];
    const float* b1   = (const float*)d_in[5];
    const float* W2   = (const float*)d_in[6];
    const float* b2   = (const float*)d_in[7];
    float* out = (float*)d_out;

    cudaFuncSetAttribute(expert_kernel,
                         cudaFuncAttributeMaxDynamicSharedMemorySize, SMEM_BYTES);

    init_kernel<<<4608, 256>>>(x, Wg, bg, bias, W1, W2);
    expert_kernel<<<EGRID, ETHREADS, SMEM_BYTES>>>(x, b1, b2, out);
}